// round 1
// baseline (speedup 1.0000x reference)
#include <cuda_runtime.h>
#include <cstdint>

#define NROWS 16384
#define KNBR  32
#define DIN   256
#define DOUT  256
#define DCAT  512

// ---------------- scratch (no allocation allowed -> device globals) ----------
__device__ float g_Mt[DIN * DIN];          // Mt[i][j] = sum_o Wk[o,i]*Wq[o,j]
__device__ float g_Wnv[DOUT * DIN];        // Wnv[o][i] = sum_d Wno[o,d]*Wv[d,i]
__device__ float g_bqk[DIN];               // (Wk^T bq)[i]
__device__ float g_veb[DIN];               // (Wq^T bk)[j]
__device__ float g_bnv[DOUT];              // Wno@bv + bno
__device__ float g_ceb;                    // bq . bk
__device__ float g_qt[NROWS * DIN];        // input @ Mt^T + bqk
__device__ float g_ctx[NROWS * DIN];       // sum_k att * nb
__device__ float g_out2[NROWS * DCAT];     // concat(self_out, neigh_out)
__device__ float g_gate[NROWS * DCAT];     // gate pre-activation
__device__ float g_part[128 * DCAT * 2];   // BN partial sums
__device__ float g_mean[DCAT];
__device__ float g_scale[DCAT];            // rsqrt(var+eps)

// ---------------- prep: fold weight matrices ---------------------------------
__global__ void prep_mats(const float* __restrict__ Wq, const float* __restrict__ Wk,
                          const float* __restrict__ Wno, const float* __restrict__ Wv) {
    int b = blockIdx.x, j = threadIdx.x;
    if (b < 256) {
        int i = b; float acc = 0.f;
        for (int o = 0; o < 256; ++o) acc += Wk[o * 256 + i] * Wq[o * 256 + j];
        g_Mt[i * 256 + j] = acc;
    } else {
        int o = b - 256; float acc = 0.f;
        for (int d = 0; d < 256; ++d) acc += Wno[o * 256 + d] * Wv[d * 256 + j];
        g_Wnv[o * 256 + j] = acc;
    }
}

__global__ void prep_bias(const float* __restrict__ Wq, const float* __restrict__ Wk,
                          const float* __restrict__ bq, const float* __restrict__ bk,
                          const float* __restrict__ Wno, const float* __restrict__ bv,
                          const float* __restrict__ bno) {
    int b = blockIdx.x, t = threadIdx.x;
    if (b == 0) {
        float a = 0.f;
        for (int o = 0; o < 256; ++o) a += bq[o] * Wk[o * 256 + t];
        g_bqk[t] = a;
    } else if (b == 1) {
        float a = 0.f;
        for (int o = 0; o < 256; ++o) a += bk[o] * Wq[o * 256 + t];
        g_veb[t] = a;
    } else if (b == 2) {
        float a = 0.f;
        for (int d = 0; d < 256; ++d) a += Wno[t * 256 + d] * bv[d];
        g_bnv[t] = a + bno[t];
    } else {
        if (t == 0) {
            float a = 0.f;
            for (int o = 0; o < 256; ++o) a += bq[o] * bk[o];
            g_ceb = a;
        }
    }
}

// ---------------- SGEMM: C[m, coff+n] = A[m,:K] . W[n,:K] + bias[n] ----------
// BM=BN=128, BK=8, TM=TN=8, 256 threads, double-buffered smem.
__global__ void __launch_bounds__(256) sgemm128(
    const float* __restrict__ A, const float* __restrict__ W,
    const float* __restrict__ bias, float* __restrict__ C,
    int K, int lda, int ldc, int coff)
{
    __shared__ float As[2][8][128];
    __shared__ float Ws[2][8][128];
    const int tid = threadIdx.x;
    const int tx = tid & 15;
    const int ty = tid >> 4;
    const int m0 = blockIdx.y * 128;
    const int n0 = blockIdx.x * 128;
    const int ldRow = tid >> 1;
    const int ldK = (tid & 1) * 4;

    const float* Ap = A + (size_t)(m0 + ldRow) * lda + ldK;
    const float* Wp = W + (size_t)(n0 + ldRow) * K + ldK;

    float4 av = *(const float4*)Ap;
    float4 wv = *(const float4*)Wp;
    As[0][ldK + 0][ldRow] = av.x; As[0][ldK + 1][ldRow] = av.y;
    As[0][ldK + 2][ldRow] = av.z; As[0][ldK + 3][ldRow] = av.w;
    Ws[0][ldK + 0][ldRow] = wv.x; Ws[0][ldK + 1][ldRow] = wv.y;
    Ws[0][ldK + 2][ldRow] = wv.z; Ws[0][ldK + 3][ldRow] = wv.w;
    __syncthreads();

    float acc[8][8] = {};
    const int ntiles = K >> 3;
    for (int t = 0; t < ntiles; ++t) {
        const int cur = t & 1;
        if (t + 1 < ntiles) {
            av = *(const float4*)(Ap + (t + 1) * 8);
            wv = *(const float4*)(Wp + (t + 1) * 8);
        }
#pragma unroll
        for (int kk = 0; kk < 8; ++kk) {
            float a[8], b[8];
            *(float4*)&a[0] = *(const float4*)&As[cur][kk][ty * 8];
            *(float4*)&a[4] = *(const float4*)&As[cur][kk][ty * 8 + 4];
            *(float4*)&b[0] = *(const float4*)&Ws[cur][kk][tx * 8];
            *(float4*)&b[4] = *(const float4*)&Ws[cur][kk][tx * 8 + 4];
#pragma unroll
            for (int i = 0; i < 8; ++i)
#pragma unroll
                for (int j = 0; j < 8; ++j)
                    acc[i][j] += a[i] * b[j];
        }
        if (t + 1 < ntiles) {
            const int nxt = cur ^ 1;
            As[nxt][ldK + 0][ldRow] = av.x; As[nxt][ldK + 1][ldRow] = av.y;
            As[nxt][ldK + 2][ldRow] = av.z; As[nxt][ldK + 3][ldRow] = av.w;
            Ws[nxt][ldK + 0][ldRow] = wv.x; Ws[nxt][ldK + 1][ldRow] = wv.y;
            Ws[nxt][ldK + 2][ldRow] = wv.z; Ws[nxt][ldK + 3][ldRow] = wv.w;
            __syncthreads();
        }
    }

    float bs[8];
#pragma unroll
    for (int j = 0; j < 8; ++j) bs[j] = bias[n0 + tx * 8 + j];
#pragma unroll
    for (int i = 0; i < 8; ++i) {
        float* crow = C + (size_t)(m0 + ty * 8 + i) * ldc + coff + n0 + tx * 8;
        float4 o0, o1;
        o0.x = acc[i][0] + bs[0]; o0.y = acc[i][1] + bs[1];
        o0.z = acc[i][2] + bs[2]; o0.w = acc[i][3] + bs[3];
        o1.x = acc[i][4] + bs[4]; o1.y = acc[i][5] + bs[5];
        o1.z = acc[i][6] + bs[6]; o1.w = acc[i][7] + bs[7];
        *(float4*)(crow) = o0;
        *(float4*)(crow + 4) = o1;
    }
}

// ---------------- fused attention: one CTA per n -----------------------------
__global__ void __launch_bounds__(256) attn_kernel(const float* __restrict__ nb,
                                                   const float* __restrict__ input) {
    const int n = blockIdx.x;
    const int tid = threadIdx.x;
    const int lane = tid & 31;
    const int w = tid >> 5;

    __shared__ float s_nb[KNBR * DIN];   // 32 KB
    __shared__ float s_qt[DIN];
    __shared__ float s_e[KNBR];
    __shared__ float s_rs[KNBR];
    __shared__ float s_att[KNBR];
    __shared__ float s_red[8];
    __shared__ float s_eb;

    s_qt[tid] = g_qt[(size_t)n * DIN + tid];

    // eb[n] = input[n] . veb + ceb
    float p = input[(size_t)n * DIN + tid] * g_veb[tid];
#pragma unroll
    for (int o = 16; o; o >>= 1) p += __shfl_xor_sync(0xffffffffu, p, o);
    if (lane == 0) s_red[w] = p;

    // stage neighbor tile: 2048 float4, 8 per thread
    const float4* src = (const float4*)(nb + (size_t)n * (KNBR * DIN));
    float4* dst = (float4*)s_nb;
#pragma unroll
    for (int i = 0; i < 8; ++i) dst[tid + 256 * i] = src[tid + 256 * i];
    __syncthreads();

    if (tid == 0) {
        float eb = 0.f;
#pragma unroll
        for (int i = 0; i < 8; ++i) eb += s_red[i];
        s_eb = eb + g_ceb;
    }

    // energies + row sums: warp w handles k = 4w..4w+3
#pragma unroll
    for (int kk = 0; kk < 4; ++kk) {
        const int k = w * 4 + kk;
        float e = 0.f, rs = 0.f;
#pragma unroll
        for (int m = 0; m < 8; ++m) {
            float v = s_nb[k * DIN + lane + 32 * m];
            rs += v;
            e += v * s_qt[lane + 32 * m];
        }
#pragma unroll
        for (int o = 16; o; o >>= 1) {
            e  += __shfl_xor_sync(0xffffffffu, e, o);
            rs += __shfl_xor_sync(0xffffffffu, rs, o);
        }
        if (lane == 0) { s_e[k] = e; s_rs[k] = rs; }
    }
    __syncthreads();

    // softmax over K=32 by warp 0 (masked rows -> energy = 1e-12, pre-shift)
    if (w == 0) {
        float e = (s_rs[lane] == 0.0f) ? 1e-12f : (s_e[lane] + s_eb);
        float m = e;
#pragma unroll
        for (int o = 16; o; o >>= 1) m = fmaxf(m, __shfl_xor_sync(0xffffffffu, m, o));
        float ex = expf(e - m);
        float s = ex;
#pragma unroll
        for (int o = 16; o; o >>= 1) s += __shfl_xor_sync(0xffffffffu, s, o);
        s_att[lane] = ex / s;
    }
    __syncthreads();

    // ctx_in[n, tid] = sum_k att[k] * nb[k, tid]
    float c = 0.f;
#pragma unroll
    for (int k = 0; k < KNBR; ++k) c += s_att[k] * s_nb[k * DIN + tid];
    g_ctx[(size_t)n * DIN + tid] = c;
}

// ---------------- BatchNorm stats (deterministic two-stage) ------------------
__global__ void __launch_bounds__(512) bn_partial() {
    const int b = blockIdx.x;       // 128 row chunks of 128 rows
    const int c = threadIdx.x;      // 512 columns
    float s = 0.f, sq = 0.f;
    const float* base = g_out2 + (size_t)b * 128 * DCAT + c;
#pragma unroll 4
    for (int r = 0; r < 128; ++r) {
        float v = base[(size_t)r * DCAT];
        s += v; sq += v * v;
    }
    g_part[(b * DCAT + c) * 2 + 0] = s;
    g_part[(b * DCAT + c) * 2 + 1] = sq;
}

__global__ void __launch_bounds__(512) bn_final() {
    const int c = threadIdx.x;
    float s = 0.f, sq = 0.f;
    for (int b = 0; b < 128; ++b) {
        s  += g_part[(b * DCAT + c) * 2 + 0];
        sq += g_part[(b * DCAT + c) * 2 + 1];
    }
    const float inv = 1.0f / (float)NROWS;
    float mean = s * inv;
    float var = sq * inv - mean * mean;
    g_mean[c] = mean;
    g_scale[c] = rsqrtf(var + 1e-5f);
}

// ---------------- final elementwise ------------------------------------------
__global__ void __launch_bounds__(256) final_kernel(const float* __restrict__ gamma,
                                                    const float* __restrict__ beta,
                                                    float* __restrict__ out) {
    const int idx = blockIdx.x * 256 + threadIdx.x;   // float4 index
    const int c4 = (idx & 127) * 4;                   // 128 float4 per row of 512
    float4 g = ((const float4*)g_gate)[idx];
    float4 o = ((const float4*)g_out2)[idx];
    float4 r;
    {
        float bn = gamma[c4 + 0] * (o.x - g_mean[c4 + 0]) * g_scale[c4 + 0] + beta[c4 + 0];
        r.x = fmaxf(g.x, 0.f) * fmaxf(bn, 0.f);
    }
    {
        float bn = gamma[c4 + 1] * (o.y - g_mean[c4 + 1]) * g_scale[c4 + 1] + beta[c4 + 1];
        r.y = fmaxf(g.y, 0.f) * fmaxf(bn, 0.f);
    }
    {
        float bn = gamma[c4 + 2] * (o.z - g_mean[c4 + 2]) * g_scale[c4 + 2] + beta[c4 + 2];
        r.z = fmaxf(g.z, 0.f) * fmaxf(bn, 0.f);
    }
    {
        float bn = gamma[c4 + 3] * (o.w - g_mean[c4 + 3]) * g_scale[c4 + 3] + beta[c4 + 3];
        r.w = fmaxf(g.w, 0.f) * fmaxf(bn, 0.f);
    }
    ((float4*)out)[idx] = r;
}

// ---------------- host launch ------------------------------------------------
extern "C" void kernel_launch(void* const* d_in, const int* in_sizes, int n_in,
                              void* d_out, int out_size) {
    (void)in_sizes; (void)n_in; (void)out_size;
    const float* input = (const float*)d_in[0];
    const float* nb    = (const float*)d_in[1];
    const float* Wq    = (const float*)d_in[2];
    const float* bq    = (const float*)d_in[3];
    const float* Wk    = (const float*)d_in[4];
    const float* bk    = (const float*)d_in[5];
    const float* Wv    = (const float*)d_in[6];
    const float* bv    = (const float*)d_in[7];
    const float* Wno   = (const float*)d_in[8];
    const float* bno   = (const float*)d_in[9];
    const float* Wio   = (const float*)d_in[10];
    const float* bio   = (const float*)d_in[11];
    const float* Wg    = (const float*)d_in[12];
    const float* bg    = (const float*)d_in[13];
    const float* gamma = (const float*)d_in[14];
    const float* beta  = (const float*)d_in[15];
    float* out = (float*)d_out;

    float *p_Mt, *p_Wnv, *p_bqk, *p_bnv, *p_qt, *p_ctx, *p_out2, *p_gate;
    cudaGetSymbolAddress((void**)&p_Mt,   g_Mt);
    cudaGetSymbolAddress((void**)&p_Wnv,  g_Wnv);
    cudaGetSymbolAddress((void**)&p_bqk,  g_bqk);
    cudaGetSymbolAddress((void**)&p_bnv,  g_bnv);
    cudaGetSymbolAddress((void**)&p_qt,   g_qt);
    cudaGetSymbolAddress((void**)&p_ctx,  g_ctx);
    cudaGetSymbolAddress((void**)&p_out2, g_out2);
    cudaGetSymbolAddress((void**)&p_gate, g_gate);

    prep_mats<<<512, 256>>>(Wq, Wk, Wno, Wv);
    prep_bias<<<4, 256>>>(Wq, Wk, bq, bk, Wno, bv, bno);

    // qt = input @ Mt^T + bqk           -> g_qt  [N,256]
    sgemm128<<<dim3(2, 128), 256>>>(input, p_Mt, p_bqk, p_qt, 256, 256, 256, 0);
    // self_out = input @ Wio^T + bio    -> g_out2 cols [0,256)
    sgemm128<<<dim3(2, 128), 256>>>(input, Wio, bio, p_out2, 256, 256, 512, 0);

    // fused attention -> g_ctx
    attn_kernel<<<NROWS, 256>>>(nb, input);

    // neigh_out = ctx @ Wnv^T + bnv     -> g_out2 cols [256,512)
    sgemm128<<<dim3(2, 128), 256>>>(p_ctx, p_Wnv, p_bnv, p_out2, 256, 256, 512, 256);

    // gate preact = out2 @ Wg^T + bg    -> g_gate [N,512]
    sgemm128<<<dim3(4, 128), 256>>>(p_out2, Wg, bg, p_gate, 512, 512, 512, 0);

    bn_partial<<<128, 512>>>();
    bn_final<<<1, 512>>>();
    final_kernel<<<(NROWS * DCAT / 4) / 256, 256>>>(gamma, beta, out);
}

// round 2
// speedup vs baseline: 1.8199x; 1.8199x over previous
#include <cuda_runtime.h>
#include <cstdint>

#define NROWS 16384
#define KNBR  32
#define DIN   256
#define DCAT  512

// ---------------- scratch (no allocation allowed -> device globals) ----------
__device__ float g_Mt[256 * 256];          // Mt[i][j] = sum_o Wk[o,i]*Wq[o,j]
__device__ float g_Wnv[256 * 256];         // Wnv[o][i] = sum_d Wno[o,d]*Wv[d,i]
__device__ float g_bqk[256];               // (Wk^T bq)[i]
__device__ float g_veb[256];               // (Wq^T bk)[j]
__device__ float g_bnv[256];               // Wno@bv + bno
__device__ float g_ceb;                    // bq . bk
__device__ float g_qt[NROWS * 256];        // input @ Mt^T + bqk
__device__ float g_ctx[NROWS * 256];       // sum_k att * nb
__device__ float g_out2[NROWS * 512];      // concat(self_out, neigh_out)
__device__ float g_part[128 * 512 * 2];    // BN partial sums
__device__ float g_mean[512];
__device__ float g_scale[512];             // rsqrt(var+eps)

// ---------------- prep: fold weight matrices ---------------------------------
__global__ void prep_mats(const float* __restrict__ Wq, const float* __restrict__ Wk,
                          const float* __restrict__ Wno, const float* __restrict__ Wv) {
    int b = blockIdx.x, j = threadIdx.x;
    if (b < 256) {
        int i = b; float acc = 0.f;
        for (int o = 0; o < 256; ++o) acc += Wk[o * 256 + i] * Wq[o * 256 + j];
        g_Mt[i * 256 + j] = acc;
    } else {
        int o = b - 256; float acc = 0.f;
        for (int d = 0; d < 256; ++d) acc += Wno[o * 256 + d] * Wv[d * 256 + j];
        g_Wnv[o * 256 + j] = acc;
    }
}

__global__ void prep_bias(const float* __restrict__ Wq, const float* __restrict__ Wk,
                          const float* __restrict__ bq, const float* __restrict__ bk,
                          const float* __restrict__ Wno, const float* __restrict__ bv,
                          const float* __restrict__ bno) {
    int b = blockIdx.x, t = threadIdx.x;
    if (b == 0) {
        float a = 0.f;
        for (int o = 0; o < 256; ++o) a += bq[o] * Wk[o * 256 + t];
        g_bqk[t] = a;
    } else if (b == 1) {
        float a = 0.f;
        for (int o = 0; o < 256; ++o) a += bk[o] * Wq[o * 256 + t];
        g_veb[t] = a;
    } else if (b == 2) {
        float a = 0.f;
        for (int d = 0; d < 256; ++d) a += Wno[t * 256 + d] * bv[d];
        g_bnv[t] = a + bno[t];
    } else {
        if (t == 0) {
            float a = 0.f;
            for (int o = 0; o < 256; ++o) a += bq[o] * bk[o];
            g_ceb = a;
        }
    }
}

// ---------------- tf32 tensor-core GEMM --------------------------------------
// C[m, coff+n] = A[m,:K] . W[n,:K] + bias[n]
// BM=BN=128, BK=32, 256 threads (8 warps, 2x4), warp tile 64x32,
// mma.sync.m16n8k8 tf32, cp.async double-buffered smem, pad 36 (conflict-free).
// MODE 0: plain bias epilogue.  MODE 1: fused gate*relu(bn(out2)) final output.

__device__ __forceinline__ void cp16(uint32_t s, const void* g) {
    asm volatile("cp.async.cg.shared.global [%0], [%1], 16;\n" :: "r"(s), "l"(g));
}
__device__ __forceinline__ uint32_t f2tf32(uint32_t x) {
    uint32_t r;
    asm("cvt.rna.tf32.f32 %0, %1;" : "=r"(r) : "r"(x));
    return r;
}

template <int MODE>
__global__ void __launch_bounds__(256, 2) mma_gemm(
    const float* __restrict__ A, const float* __restrict__ W,
    const float* __restrict__ bias, float* __restrict__ C,
    int K, int ldc, int coff,
    const float* __restrict__ gamma, const float* __restrict__ beta,
    float* __restrict__ outp)
{
    extern __shared__ uint32_t sm[];       // As[2][128][36] | Ws[2][128][36]
    uint32_t* As = sm;
    uint32_t* Ws = sm + 9216;

    const int tid = threadIdx.x;
    const int lane = tid & 31, warp = tid >> 5;
    const int wm = warp >> 2, wn = warp & 3;       // warp grid 2x4
    const int g = lane >> 2, tg = lane & 3;
    const int m0 = blockIdx.y * 128, n0 = blockIdx.x * 128;

    // global load mapping: 4 x float4 per thread per tile, rows rL+32i, col cL
    const int rL = tid >> 3;
    const int cL = (tid & 7) * 4;
    const float* Agp = A + (size_t)(m0 + rL) * K + cL;
    const float* Wgp = W + (size_t)(n0 + rL) * K + cL;
    const uint32_t sbase = (uint32_t)__cvta_generic_to_shared(sm);

    float acc[4][4][4];
#pragma unroll
    for (int i = 0; i < 4; ++i)
#pragma unroll
        for (int j = 0; j < 4; ++j)
#pragma unroll
            for (int h = 0; h < 4; ++h) acc[i][j][h] = 0.f;

    const int nt = K >> 5;

#define ISSUE_TILE(T, BUF)                                                          \
    {                                                                               \
        _Pragma("unroll")                                                           \
        for (int i = 0; i < 4; ++i) {                                               \
            int rr = rL + 32 * i;                                                   \
            cp16(sbase + 4u * ((BUF) * 4608 + rr * 36 + cL),                        \
                 Agp + (size_t)32 * i * K + (T) * 32);                              \
            cp16(sbase + 4u * (9216 + (BUF) * 4608 + rr * 36 + cL),                 \
                 Wgp + (size_t)32 * i * K + (T) * 32);                              \
        }                                                                           \
        asm volatile("cp.async.commit_group;\n");                                   \
    }

    ISSUE_TILE(0, 0);
    asm volatile("cp.async.wait_group 0;\n");
    __syncthreads();

    for (int t = 0; t < nt; ++t) {
        const int buf = t & 1;
        if (t + 1 < nt) ISSUE_TILE(t + 1, buf ^ 1);

        const uint32_t* Ab = As + buf * 4608;
        const uint32_t* Wb = Ws + buf * 4608;
#pragma unroll
        for (int ks = 0; ks < 4; ++ks) {
            const int kk = ks * 8;
            uint32_t a[4][4], b[4][2];
#pragma unroll
            for (int mf = 0; mf < 4; ++mf) {
                const int r = wm * 64 + mf * 16 + g;
                a[mf][0] = f2tf32(Ab[r * 36 + kk + tg]);
                a[mf][1] = f2tf32(Ab[(r + 8) * 36 + kk + tg]);
                a[mf][2] = f2tf32(Ab[r * 36 + kk + tg + 4]);
                a[mf][3] = f2tf32(Ab[(r + 8) * 36 + kk + tg + 4]);
            }
#pragma unroll
            for (int nf = 0; nf < 4; ++nf) {
                const int c = wn * 32 + nf * 8 + g;
                b[nf][0] = f2tf32(Wb[c * 36 + kk + tg]);
                b[nf][1] = f2tf32(Wb[c * 36 + kk + tg + 4]);
            }
#pragma unroll
            for (int mf = 0; mf < 4; ++mf)
#pragma unroll
                for (int nf = 0; nf < 4; ++nf)
                    asm volatile(
                        "mma.sync.aligned.m16n8k8.row.col.f32.tf32.tf32.f32 "
                        "{%0,%1,%2,%3},{%4,%5,%6,%7},{%8,%9},{%0,%1,%2,%3};\n"
                        : "+f"(acc[mf][nf][0]), "+f"(acc[mf][nf][1]),
                          "+f"(acc[mf][nf][2]), "+f"(acc[mf][nf][3])
                        : "r"(a[mf][0]), "r"(a[mf][1]), "r"(a[mf][2]), "r"(a[mf][3]),
                          "r"(b[nf][0]), "r"(b[nf][1]));
        }
        if (t + 1 < nt) {
            asm volatile("cp.async.wait_group 0;\n");
            __syncthreads();
        }
    }

    // epilogue
#pragma unroll
    for (int mf = 0; mf < 4; ++mf) {
        const int r0 = m0 + wm * 64 + mf * 16 + g;
#pragma unroll
        for (int nf = 0; nf < 4; ++nf) {
            const int c = n0 + wn * 32 + nf * 8 + 2 * tg;
            if (MODE == 0) {
                const float b0 = bias[c], b1 = bias[c + 1];
                float2 v0 = make_float2(acc[mf][nf][0] + b0, acc[mf][nf][1] + b1);
                float2 v1 = make_float2(acc[mf][nf][2] + b0, acc[mf][nf][3] + b1);
                *(float2*)&C[(size_t)r0 * ldc + coff + c] = v0;
                *(float2*)&C[(size_t)(r0 + 8) * ldc + coff + c] = v1;
            } else {
#pragma unroll
                for (int h = 0; h < 2; ++h) {
                    const int r = r0 + 8 * h;
                    float2 res;
#pragma unroll
                    for (int j = 0; j < 2; ++j) {
                        const int cc = c + j;
                        float pre = acc[mf][nf][2 * h + j] + bias[cc];
                        float o = g_out2[(size_t)r * 512 + cc];
                        float bnv = gamma[cc] * (o - g_mean[cc]) * g_scale[cc] + beta[cc];
                        float v = fmaxf(pre, 0.f) * fmaxf(bnv, 0.f);
                        if (j == 0) res.x = v; else res.y = v;
                    }
                    *(float2*)&outp[(size_t)r * 512 + c] = res;
                }
            }
        }
    }
#undef ISSUE_TILE
}

// ---------------- fused attention: one CTA per n -----------------------------
__global__ void __launch_bounds__(256) attn_kernel(const float* __restrict__ nb,
                                                   const float* __restrict__ input) {
    const int n = blockIdx.x;
    const int tid = threadIdx.x;
    const int lane = tid & 31;
    const int w = tid >> 5;

    __shared__ float s_nb[KNBR * DIN];   // 32 KB
    __shared__ float s_qt[DIN];
    __shared__ float s_e[KNBR];
    __shared__ float s_rs[KNBR];
    __shared__ float s_att[KNBR];
    __shared__ float s_red[8];
    __shared__ float s_eb;

    s_qt[tid] = g_qt[(size_t)n * DIN + tid];

    // eb[n] = input[n] . veb + ceb
    float p = input[(size_t)n * DIN + tid] * g_veb[tid];
#pragma unroll
    for (int o = 16; o; o >>= 1) p += __shfl_xor_sync(0xffffffffu, p, o);
    if (lane == 0) s_red[w] = p;

    // stage neighbor tile: 2048 float4, 8 per thread
    const float4* src = (const float4*)(nb + (size_t)n * (KNBR * DIN));
    float4* dst = (float4*)s_nb;
#pragma unroll
    for (int i = 0; i < 8; ++i) dst[tid + 256 * i] = src[tid + 256 * i];
    __syncthreads();

    if (tid == 0) {
        float eb = 0.f;
#pragma unroll
        for (int i = 0; i < 8; ++i) eb += s_red[i];
        s_eb = eb + g_ceb;
    }

    // energies + row sums: warp w handles k = 4w..4w+3
#pragma unroll
    for (int kk = 0; kk < 4; ++kk) {
        const int k = w * 4 + kk;
        float e = 0.f, rs = 0.f;
#pragma unroll
        for (int m = 0; m < 8; ++m) {
            float v = s_nb[k * DIN + lane + 32 * m];
            rs += v;
            e += v * s_qt[lane + 32 * m];
        }
#pragma unroll
        for (int o = 16; o; o >>= 1) {
            e  += __shfl_xor_sync(0xffffffffu, e, o);
            rs += __shfl_xor_sync(0xffffffffu, rs, o);
        }
        if (lane == 0) { s_e[k] = e; s_rs[k] = rs; }
    }
    __syncthreads();

    // softmax over K=32 by warp 0 (masked rows -> energy = 1e-12, pre-shift)
    if (w == 0) {
        float e = (s_rs[lane] == 0.0f) ? 1e-12f : (s_e[lane] + s_eb);
        float m = e;
#pragma unroll
        for (int o = 16; o; o >>= 1) m = fmaxf(m, __shfl_xor_sync(0xffffffffu, m, o));
        float ex = expf(e - m);
        float s = ex;
#pragma unroll
        for (int o = 16; o; o >>= 1) s += __shfl_xor_sync(0xffffffffu, s, o);
        s_att[lane] = ex / s;
    }
    __syncthreads();

    // ctx_in[n, tid] = sum_k att[k] * nb[k, tid]
    float c = 0.f;
#pragma unroll
    for (int k = 0; k < KNBR; ++k) c += s_att[k] * s_nb[k * DIN + tid];
    g_ctx[(size_t)n * DIN + tid] = c;
}

// ---------------- BatchNorm stats (deterministic two-stage) ------------------
__global__ void __launch_bounds__(512) bn_partial() {
    const int b = blockIdx.x;       // 128 row chunks of 128 rows
    const int c = threadIdx.x;      // 512 columns
    float s = 0.f, sq = 0.f;
    const float* base = g_out2 + (size_t)b * 128 * DCAT + c;
#pragma unroll 4
    for (int r = 0; r < 128; ++r) {
        float v = base[(size_t)r * DCAT];
        s += v; sq += v * v;
    }
    g_part[(b * DCAT + c) * 2 + 0] = s;
    g_part[(b * DCAT + c) * 2 + 1] = sq;
}

__global__ void __launch_bounds__(512) bn_final() {
    const int c = threadIdx.x;
    float s = 0.f, sq = 0.f;
    for (int b = 0; b < 128; ++b) {
        s  += g_part[(b * DCAT + c) * 2 + 0];
        sq += g_part[(b * DCAT + c) * 2 + 1];
    }
    const float inv = 1.0f / (float)NROWS;
    float mean = s * inv;
    float var = sq * inv - mean * mean;
    g_mean[c] = mean;
    g_scale[c] = rsqrtf(var + 1e-5f);
}

// ---------------- host launch ------------------------------------------------
extern "C" void kernel_launch(void* const* d_in, const int* in_sizes, int n_in,
                              void* d_out, int out_size) {
    (void)in_sizes; (void)n_in; (void)out_size;
    const float* input = (const float*)d_in[0];
    const float* nb    = (const float*)d_in[1];
    const float* Wq    = (const float*)d_in[2];
    const float* bq    = (const float*)d_in[3];
    const float* Wk    = (const float*)d_in[4];
    const float* bk    = (const float*)d_in[5];
    const float* Wv    = (const float*)d_in[6];
    const float* bv    = (const float*)d_in[7];
    const float* Wno   = (const float*)d_in[8];
    const float* bno   = (const float*)d_in[9];
    const float* Wio   = (const float*)d_in[10];
    const float* bio   = (const float*)d_in[11];
    const float* Wg    = (const float*)d_in[12];
    const float* bg    = (const float*)d_in[13];
    const float* gamma = (const float*)d_in[14];
    const float* beta  = (const float*)d_in[15];
    float* out = (float*)d_out;

    float *p_Mt, *p_Wnv, *p_bqk, *p_bnv, *p_qt, *p_ctx, *p_out2;
    cudaGetSymbolAddress((void**)&p_Mt,   g_Mt);
    cudaGetSymbolAddress((void**)&p_Wnv,  g_Wnv);
    cudaGetSymbolAddress((void**)&p_bqk,  g_bqk);
    cudaGetSymbolAddress((void**)&p_bnv,  g_bnv);
    cudaGetSymbolAddress((void**)&p_qt,   g_qt);
    cudaGetSymbolAddress((void**)&p_ctx,  g_ctx);
    cudaGetSymbolAddress((void**)&p_out2, g_out2);

    static bool attr_done = false;
    if (!attr_done) {
        cudaFuncSetAttribute(mma_gemm<0>, cudaFuncAttributeMaxDynamicSharedMemorySize, 73728);
        cudaFuncSetAttribute(mma_gemm<1>, cudaFuncAttributeMaxDynamicSharedMemorySize, 73728);
        attr_done = true;
    }
    const int SMEM = 73728;

    prep_mats<<<512, 256>>>(Wq, Wk, Wno, Wv);
    prep_bias<<<4, 256>>>(Wq, Wk, bq, bk, Wno, bv, bno);

    // qt = input @ Mt^T + bqk           -> g_qt  [N,256]
    mma_gemm<0><<<dim3(2, 128), 256, SMEM>>>(input, p_Mt, p_bqk, p_qt,
                                             256, 256, 0, nullptr, nullptr, nullptr);
    // self_out = input @ Wio^T + bio    -> g_out2 cols [0,256)
    mma_gemm<0><<<dim3(2, 128), 256, SMEM>>>(input, Wio, bio, p_out2,
                                             256, 512, 0, nullptr, nullptr, nullptr);

    // fused attention -> g_ctx
    attn_kernel<<<NROWS, 256>>>(nb, input);

    // neigh_out = ctx @ Wnv^T + bnv     -> g_out2 cols [256,512)
    mma_gemm<0><<<dim3(2, 128), 256, SMEM>>>(p_ctx, p_Wnv, p_bnv, p_out2,
                                             256, 512, 256, nullptr, nullptr, nullptr);

    // BN stats on out2 (needed by fused gate epilogue)
    bn_partial<<<128, 512>>>();
    bn_final<<<1, 512>>>();

    // gate GEMM fused with final elementwise: out = relu(out2@Wg^T+bg) * relu(bn(out2))
    mma_gemm<1><<<dim3(4, 128), 256, SMEM>>>(p_out2, Wg, bg, nullptr,
                                             512, 512, 0, gamma, beta, out);
}